// round 6
// baseline (speedup 1.0000x reference)
#include <cuda_runtime.h>
#include <cuda_bf16.h>
#include <math.h>
#include <stdint.h>

#define T_STEPS 64
#define BATCH   512
#define DET     1024
#define STO     128
#define EMB     1024
#define ACTD    16
#define MLP     1024
#define OUTW    1536            // 4*STO + DET
#define XIN     (STO + ACTD)    // 144
#define XINP    192             // padded K for input GEMM
#define MIN_STD 0.1f

// ---------------- GEMM tiling ----------------
#define BM 128
#define BN 128
#define BKP 64                  // K' elements per tile (bf16)
#define TILE_B 16384            // 128 rows * 128B
#define STAGE_B 32768           // A tile + W tile
#define NSTAGE 3
#define SMEM_TOT (NSTAGE * STAGE_B)   // 98304

typedef __nv_bfloat16 bf16;

// ---------------- scratch (device globals; no allocation allowed) ----------------
__device__ float g_hprev[BATCH*DET];
__device__ float g_gi   [BATCH*3*DET];
__device__ float g_gh   [BATCH*3*DET];

__device__ bf16 g_hprev_h[BATCH*DET],  g_hprev_l[BATCH*DET];
__device__ bf16 g_xin_h  [BATCH*XINP], g_xin_l  [BATCH*XINP];
__device__ bf16 g_x_h    [BATCH*DET],  g_x_l    [BATCH*DET];
__device__ bf16 g_q1_h   [BATCH*MLP],  g_q1_l   [BATCH*MLP];
__device__ bf16 g_hT_h   [(size_t)T_STEPS*BATCH*DET], g_hT_l[(size_t)T_STEPS*BATCH*DET];
__device__ bf16 g_obs_h  [(size_t)T_STEPS*BATCH*EMB], g_obs_l[(size_t)T_STEPS*BATCH*EMB];
__device__ bf16 g_p1_h   [(size_t)T_STEPS*BATCH*MLP], g_p1_l[(size_t)T_STEPS*BATCH*MLP];

// triple-K weights: [N, 3K] = [Wh | Wh | Wl]
__device__ bf16 g_Wih3[(size_t)3*DET*3*DET];
__device__ bf16 g_Whh3[(size_t)3*DET*3*DET];
__device__ bf16 g_Wq13[(size_t)MLP*3*(DET+EMB)];
__device__ bf16 g_Wq23[(size_t)2*STO*3*MLP];
__device__ bf16 g_Wp13[(size_t)MLP*3*DET];
__device__ bf16 g_Wp23[(size_t)2*STO*3*MLP];
__device__ bf16 g_Win3[(size_t)DET*3*XINP];

// ---------------- math helpers ----------------
__device__ __forceinline__ float elu_f(float v)      { return v > 0.0f ? v : expm1f(v); }
__device__ __forceinline__ float softplus_f(float v) { return fmaxf(v, 0.0f) + log1pf(expf(-fabsf(v))); }
__device__ __forceinline__ float sigmoid_f(float v)  { return __fdividef(1.0f, 1.0f + __expf(-v)); }
__device__ __forceinline__ float tanh_f(float x) {
    float e = __expf(-2.0f * fabsf(x));
    float r = __fdividef(1.0f - e, 1.0f + e);
    return x < 0.0f ? -r : r;
}

__device__ __forceinline__ uint32_t smem_u32(const void* p) {
    uint32_t a;
    asm("{ .reg .u64 t; cvta.to.shared.u64 t, %1; cvt.u32.u64 %0, t; }" : "=r"(a) : "l"(p));
    return a;
}
__device__ __forceinline__ void cp16(uint32_t dst, const void* src) {
    asm volatile("cp.async.cg.shared.global [%0], [%1], 16;" :: "r"(dst), "l"(src));
}
__device__ __forceinline__ void ldsm4(uint32_t* r, uint32_t addr) {
    asm volatile("ldmatrix.sync.aligned.m8n8.x4.shared.b16 {%0,%1,%2,%3}, [%4];"
                 : "=r"(r[0]), "=r"(r[1]), "=r"(r[2]), "=r"(r[3]) : "r"(addr));
}
__device__ __forceinline__ void mma16816(float* c, const uint32_t* a, uint32_t b0, uint32_t b1) {
    asm volatile("mma.sync.aligned.m16n8k16.row.col.f32.bf16.bf16.f32 "
                 "{%0,%1,%2,%3}, {%4,%5,%6,%7}, {%8,%9}, {%0,%1,%2,%3};"
                 : "+f"(c[0]), "+f"(c[1]), "+f"(c[2]), "+f"(c[3])
                 : "r"(a[0]), "r"(a[1]), "r"(a[2]), "r"(a[3]), "r"(b0), "r"(b1));
}
// Dekker split: hi = bf16 truncation, lo = bf16(v - hi) (residual exact in bf16)
__device__ __forceinline__ void split1(float v, uint16_t& h, uint16_t& l) {
    uint32_t u = __float_as_uint(v);
    float rem  = v - __uint_as_float(u & 0xFFFF0000u);
    h = (uint16_t)(u >> 16);
    l = (uint16_t)(__float_as_uint(rem) >> 16);
}
__device__ __forceinline__ void pack2(float a, float b, uint32_t& hi, uint32_t& lo) {
    uint32_t ua = __float_as_uint(a), ub = __float_as_uint(b);
    float ra = a - __uint_as_float(ua & 0xFFFF0000u);
    float rb = b - __uint_as_float(ub & 0xFFFF0000u);
    hi = (ua >> 16) | (ub & 0xFFFF0000u);
    lo = (__float_as_uint(ra) >> 16) | (__float_as_uint(rb) & 0xFFFF0000u);
}
__device__ __forceinline__ int swoff(int row, int u) {
    return row * 128 + (((u ^ (row & 7)) & 7) << 4);
}

// ---------------- GEMM params ----------------
struct GP {
    const bf16 *Ah0, *Al0, *Ah1, *Al1;   // A = K-concat(seg0, seg1); hi/lo sources
    int lda0, lda1, k0len, K;            // K = base (pre-triple) depth
    const bf16* W3;                      // [N, 3K]
    const float* bias;
    float* C; int ldc;                   // epi 0 / 2
    bf16 *Ch, *Cl; int ldch;             // epi 1 (bf16 hi/lo outputs)
    int nkb;                             // 3K / 64
    int nbx;                             // valid grid.x
    int epi;                             // 0=bias, 1=bias+elu->bf16 pair, 2=meanstd
};

// ---------------- bf16 HMMA GEMM: C = epi(A3 @ W3^T + bias) ----------------
__global__ __launch_bounds__(256, 2)
void gemm_tc(GP p0, GP p1)
{
    GP p = (blockIdx.z == 0) ? p0 : p1;
    if ((int)blockIdx.x >= p.nbx) return;

    extern __shared__ char smem[];
    const uint32_t sbase = smem_u32(smem);
    const int tid  = threadIdx.x, wid = tid >> 5, lane = tid & 31;
    const int m0   = blockIdx.y * BM, n0 = blockIdx.x * BN;
    const int wm   = (wid & 1) * 64, wn = (wid >> 1) * 32;
    const int lrow = tid >> 1;             // 0..127
    const int ub   = (tid & 1) * 4;        // unit base 0 or 4

    float acc[4][4][4];
    #pragma unroll
    for (int i = 0; i < 4; i++)
        #pragma unroll
        for (int j = 0; j < 4; j++)
            #pragma unroll
            for (int q = 0; q < 4; q++) acc[i][j][q] = 0.0f;

    auto load_stage = [&](int st, int kb) {
        const int kp = kb * BKP;
        const int phase = kp / p.K;
        const int khat  = kp - phase * p.K;
        const bf16* asrc; int acol, ald;
        if (khat < p.k0len) {
            asrc = (phase == 1) ? p.Al0 : p.Ah0; acol = khat; ald = p.lda0;
        } else {
            asrc = (phase == 1) ? p.Al1 : p.Ah1; acol = khat - p.k0len; ald = p.lda1;
        }
        const bf16* ap = asrc + (size_t)(m0 + lrow) * ald + acol + ub * 8;
        const bf16* wp = p.W3 + (size_t)(n0 + lrow) * (3 * p.K) + kp + ub * 8;
        const uint32_t As = sbase + st * STAGE_B;
        const uint32_t Ws = As + TILE_B;
        #pragma unroll
        for (int i = 0; i < 4; i++) {
            const int off = swoff(lrow, ub + i);
            cp16(As + off, ap + i * 8);
            cp16(Ws + off, wp + i * 8);
        }
        asm volatile("cp.async.commit_group;" ::: "memory");
    };

    auto compute = [&](int st) {
        const uint32_t a_s = sbase + st * STAGE_B;
        const uint32_t w_s = a_s + TILE_B;
        #pragma unroll
        for (int k16 = 0; k16 < 4; k16++) {
            uint32_t a[4][4], b[2][4];
            const int u = k16 * 2 + (lane >> 4);
            #pragma unroll
            for (int mi = 0; mi < 4; mi++)
                ldsm4(a[mi], a_s + swoff(wm + mi * 16 + (lane & 15), u));
            #pragma unroll
            for (int nj = 0; nj < 2; nj++)
                ldsm4(b[nj], w_s + swoff(wn + nj * 16 + (lane & 15), u));
            #pragma unroll
            for (int mi = 0; mi < 4; mi++)
                #pragma unroll
                for (int ni = 0; ni < 4; ni++) {
                    const int nj = ni >> 1, s = ni & 1;
                    mma16816(acc[mi][ni], a[mi], b[nj][s], b[nj][s + 2]);
                }
        }
    };

    int fetch = 0;
    #pragma unroll
    for (int s = 0; s < NSTAGE - 1; s++) { load_stage(s, fetch); fetch++; }

    for (int kb = 0; kb < p.nkb; kb++) {
        if (kb < p.nkb - 1) asm volatile("cp.async.wait_group 1;" ::: "memory");
        else                asm volatile("cp.async.wait_group 0;" ::: "memory");
        __syncthreads();
        if (fetch < p.nkb) { load_stage(fetch % NSTAGE, fetch); fetch++; }
        compute(kb % NSTAGE);
    }

    // ---- epilogue ----
    #pragma unroll
    for (int mi = 0; mi < 4; mi++) {
        const int r0 = m0 + wm + mi * 16 + (lane >> 2);
        const int r1 = r0 + 8;
        #pragma unroll
        for (int ni = 0; ni < 4; ni++) {
            const int col = n0 + wn + ni * 8 + (lane & 3) * 2;
            float b0 = p.bias[col], b1 = p.bias[col + 1];
            float e0 = acc[mi][ni][0] + b0, e1 = acc[mi][ni][1] + b1;
            float e2 = acc[mi][ni][2] + b0, e3 = acc[mi][ni][3] + b1;
            if (p.epi == 1) {
                e0 = elu_f(e0); e1 = elu_f(e1); e2 = elu_f(e2); e3 = elu_f(e3);
                uint32_t h01, l01, h23, l23;
                pack2(e0, e1, h01, l01);
                pack2(e2, e3, h23, l23);
                *(uint32_t*)(p.Ch + (size_t)r0 * p.ldch + col) = h01;
                *(uint32_t*)(p.Cl + (size_t)r0 * p.ldch + col) = l01;
                *(uint32_t*)(p.Ch + (size_t)r1 * p.ldch + col) = h23;
                *(uint32_t*)(p.Cl + (size_t)r1 * p.ldch + col) = l23;
            } else {
                if (p.epi == 2 && col >= 128) {
                    e0 = softplus_f(e0) + MIN_STD; e1 = softplus_f(e1) + MIN_STD;
                    e2 = softplus_f(e2) + MIN_STD; e3 = softplus_f(e3) + MIN_STD;
                }
                *(float2*)(p.C + (size_t)r0 * p.ldc + col) = make_float2(e0, e1);
                *(float2*)(p.C + (size_t)r1 * p.ldc + col) = make_float2(e2, e3);
            }
        }
    }
}

// ---------------- weight prep: W3 = [Wh | Wh | Wl] along K ----------------
__global__ void build_w3(const float* __restrict__ src, bf16* __restrict__ dst,
                         int K, int total)
{
    int i = blockIdx.x * blockDim.x + threadIdx.x;
    if (i >= total) return;
    int n = i / K, k = i - n * K;
    uint16_t h, l;
    split1(src[i], h, l);
    bf16* row = dst + (size_t)n * 3 * K;
    row[k]         = __ushort_as_bfloat16(h);
    row[K + k]     = __ushort_as_bfloat16(h);
    row[2 * K + k] = __ushort_as_bfloat16(l);
}
__global__ void build_w3_pad(const float* __restrict__ src, bf16* __restrict__ dst,
                             int Ksrc, int Kdst, int total)
{
    int i = blockIdx.x * blockDim.x + threadIdx.x;
    if (i >= total) return;
    int n = i / Kdst, k = i - n * Kdst;
    float v = (k < Ksrc) ? src[(size_t)n * Ksrc + k] : 0.0f;
    uint16_t h, l;
    split1(v, h, l);
    bf16* row = dst + (size_t)n * 3 * Kdst;
    row[k]            = __ushort_as_bfloat16(h);
    row[Kdst + k]     = __ushort_as_bfloat16(h);
    row[2 * Kdst + k] = __ushort_as_bfloat16(l);
}
__global__ void split_obs(const float* __restrict__ src, int total)
{
    int i = blockIdx.x * blockDim.x + threadIdx.x;
    if (i >= total) return;
    uint16_t h, l;
    split1(src[i], h, l);
    g_obs_h[i] = __ushort_as_bfloat16(h);
    g_obs_l[i] = __ushort_as_bfloat16(l);
}

// ---------------- elementwise kernels ----------------
__global__ void init_pre(const float* __restrict__ init_stoc,
                         const float* __restrict__ init_deter,
                         const float* __restrict__ nont,
                         const float* __restrict__ actions)
{
    int idx = blockIdx.x * blockDim.x + threadIdx.x;   // BATCH*DET
    int b = idx >> 10, j = idx & 1023;
    float nt = nont[b];
    float hp = init_deter[idx] * nt;
    g_hprev[idx] = hp;
    uint16_t h, l;
    split1(hp, h, l);
    g_hprev_h[idx] = __ushort_as_bfloat16(h);
    g_hprev_l[idx] = __ushort_as_bfloat16(l);
    if (j < XINP) {
        float v = 0.0f;
        if (j < STO)       v = init_stoc[b * STO + j] * nt;
        else if (j < XIN)  v = actions[(size_t)b * ACTD + (j - STO)];
        split1(v, h, l);
        g_xin_h[b * XINP + j] = __ushort_as_bfloat16(h);
        g_xin_l[b * XINP + j] = __ushort_as_bfloat16(l);
    }
}

__global__ void gru_gates(float* __restrict__ out, int t)
{
    int idx = blockIdx.x * blockDim.x + threadIdx.x;   // BATCH*DET
    int b = idx >> 10, j = idx & 1023;
    const float* gi = g_gi + (size_t)b * 3 * DET;
    const float* gh = g_gh + (size_t)b * 3 * DET;
    float r = sigmoid_f(gi[j]           + gh[j]);
    float z = sigmoid_f(gi[DET + j]     + gh[DET + j]);
    float n = tanh_f   (gi[2 * DET + j] + r * gh[2 * DET + j]);
    float h = (1.0f - z) * n + z * g_hprev[idx];
    out[((size_t)t * BATCH + b) * OUTW + 4 * STO + j] = h;
    uint16_t hh, hl;
    split1(h, hh, hl);
    size_t o = ((size_t)t * BATCH + b) * DET + j;
    g_hT_h[o] = __ushort_as_bfloat16(hh);
    g_hT_l[o] = __ushort_as_bfloat16(hl);
}

__global__ void stoc_pre(const float* __restrict__ out,
                         const float* __restrict__ noise,
                         const float* __restrict__ nont,
                         const float* __restrict__ actions,
                         int t)
{
    int idx = blockIdx.x * blockDim.x + threadIdx.x;   // BATCH*DET
    int b = idx >> 10, j = idx & 1023;
    float nt = nont[(t + 1) * BATCH + b];
    const float* row = out + ((size_t)t * BATCH + b) * OUTW;
    float hp = row[4 * STO + j] * nt;      // h from output buffer
    g_hprev[idx] = hp;
    uint16_t h, l;
    split1(hp, h, l);
    g_hprev_h[idx] = __ushort_as_bfloat16(h);
    g_hprev_l[idx] = __ushort_as_bfloat16(l);
    if (j < XIN) {
        float v;
        if (j < STO) {
            float s = row[2 * STO + j] + row[3 * STO + j] * noise[((size_t)t * BATCH + b) * STO + j];
            v = s * nt;
        } else {
            v = actions[((size_t)(t + 1) * BATCH + b) * ACTD + (j - STO)];
        }
        split1(v, h, l);
        g_xin_h[b * XINP + j] = __ushort_as_bfloat16(h);
        g_xin_l[b * XINP + j] = __ushort_as_bfloat16(l);
    }
}

// ---------------- launch ----------------
extern "C" void kernel_launch(void* const* d_in, const int* in_sizes, int n_in,
                              void* d_out, int out_size)
{
    const float* actions    = (const float*)d_in[0];
    const float* nont       = (const float*)d_in[1];
    const float* obs        = (const float*)d_in[2];
    const float* noise      = (const float*)d_in[3];
    const float* init_stoc  = (const float*)d_in[4];
    const float* init_deter = (const float*)d_in[5];
    const float* W_in = (const float*)d_in[6];
    const float* b_in = (const float*)d_in[7];
    const float* W_ih = (const float*)d_in[8];
    const float* W_hh = (const float*)d_in[9];
    const float* b_ih = (const float*)d_in[10];
    const float* b_hh = (const float*)d_in[11];
    const float* Wp1  = (const float*)d_in[12];
    const float* bp1  = (const float*)d_in[13];
    const float* Wp2  = (const float*)d_in[14];
    const float* bp2  = (const float*)d_in[15];
    const float* Wq1  = (const float*)d_in[16];
    const float* bq1  = (const float*)d_in[17];
    const float* Wq2  = (const float*)d_in[18];
    const float* bq2  = (const float*)d_in[19];
    float* out = (float*)d_out;

    float *p_hprev, *p_gi, *p_gh;
    cudaGetSymbolAddress((void**)&p_hprev, g_hprev);
    cudaGetSymbolAddress((void**)&p_gi,    g_gi);
    cudaGetSymbolAddress((void**)&p_gh,    g_gh);

    bf16 *hprev_h, *hprev_l, *xin_h, *xin_l, *x_h, *x_l, *q1_h, *q1_l;
    bf16 *hT_h, *hT_l, *obs_h, *obs_l, *p1_h, *p1_l;
    bf16 *wih3, *whh3, *wq13, *wq23, *wp13, *wp23, *win3;
    cudaGetSymbolAddress((void**)&hprev_h, g_hprev_h);
    cudaGetSymbolAddress((void**)&hprev_l, g_hprev_l);
    cudaGetSymbolAddress((void**)&xin_h,   g_xin_h);
    cudaGetSymbolAddress((void**)&xin_l,   g_xin_l);
    cudaGetSymbolAddress((void**)&x_h,     g_x_h);
    cudaGetSymbolAddress((void**)&x_l,     g_x_l);
    cudaGetSymbolAddress((void**)&q1_h,    g_q1_h);
    cudaGetSymbolAddress((void**)&q1_l,    g_q1_l);
    cudaGetSymbolAddress((void**)&hT_h,    g_hT_h);
    cudaGetSymbolAddress((void**)&hT_l,    g_hT_l);
    cudaGetSymbolAddress((void**)&obs_h,   g_obs_h);
    cudaGetSymbolAddress((void**)&obs_l,   g_obs_l);
    cudaGetSymbolAddress((void**)&p1_h,    g_p1_h);
    cudaGetSymbolAddress((void**)&p1_l,    g_p1_l);
    cudaGetSymbolAddress((void**)&wih3,    g_Wih3);
    cudaGetSymbolAddress((void**)&whh3,    g_Whh3);
    cudaGetSymbolAddress((void**)&wq13,    g_Wq13);
    cudaGetSymbolAddress((void**)&wq23,    g_Wq23);
    cudaGetSymbolAddress((void**)&wp13,    g_Wp13);
    cudaGetSymbolAddress((void**)&wp23,    g_Wp23);
    cudaGetSymbolAddress((void**)&win3,    g_Win3);

    cudaFuncSetAttribute(gemm_tc, cudaFuncAttributeMaxDynamicSharedMemorySize, SMEM_TOT);

    // ---- prep (once per launch; deterministic) ----
    build_w3<<<(3*DET*DET + 255)/256, 256>>>(W_ih, wih3, DET, 3*DET*DET);
    build_w3<<<(3*DET*DET + 255)/256, 256>>>(W_hh, whh3, DET, 3*DET*DET);
    build_w3<<<(MLP*(DET+EMB) + 255)/256, 256>>>(Wq1, wq13, DET+EMB, MLP*(DET+EMB));
    build_w3<<<(2*STO*MLP + 255)/256, 256>>>(Wq2, wq23, MLP, 2*STO*MLP);
    build_w3<<<(MLP*DET + 255)/256, 256>>>(Wp1, wp13, DET, MLP*DET);
    build_w3<<<(2*STO*MLP + 255)/256, 256>>>(Wp2, wp23, MLP, 2*STO*MLP);
    build_w3_pad<<<(DET*XINP + 255)/256, 256>>>(W_in, win3, XIN, XINP, DET*XINP);
    split_obs<<<(T_STEPS*BATCH*EMB + 255)/256, 256>>>(obs, T_STEPS*BATCH*EMB);

    init_pre<<<BATCH * DET / 256, 256>>>(init_stoc, init_deter, nont, actions);

    const int BIG = 1 << 28;
    for (int t = 0; t < T_STEPS; t++) {
        // gh = hprev @ W_hh^T + b_hh (z=0)  ||  x = elu(xin @ W_in^T + b_in) (z=1)
        GP ggh = { hprev_h, hprev_l, hprev_h, hprev_l, DET, DET, BIG, DET,
                   whh3, b_hh, p_gh, 3*DET, nullptr, nullptr, 0, 3*DET/BKP, 3*DET/BN, 0 };
        GP ggx = { xin_h, xin_l, xin_h, xin_l, XINP, XINP, BIG, XINP,
                   win3, b_in, nullptr, 0, x_h, x_l, DET, 3*XINP/BKP, DET/BN, 1 };
        gemm_tc<<<dim3(3*DET/BN, BATCH/BM, 2), 256, SMEM_TOT>>>(ggh, ggx);

        // gi = x @ W_ih^T + b_ih
        GP ggi = { x_h, x_l, x_h, x_l, DET, DET, BIG, DET,
                   wih3, b_ih, p_gi, 3*DET, nullptr, nullptr, 0, 3*DET/BKP, 3*DET/BN, 0 };
        gemm_tc<<<dim3(3*DET/BN, BATCH/BM, 1), 256, SMEM_TOT>>>(ggi, ggi);

        gru_gates<<<BATCH * DET / 256, 256>>>(out, t);

        // q1 = elu([h, obs_t] @ Wq1^T + bq1), K-concat at 1024
        GP gq1 = { hT_h + (size_t)t*BATCH*DET, hT_l + (size_t)t*BATCH*DET,
                   obs_h + (size_t)t*BATCH*EMB, obs_l + (size_t)t*BATCH*EMB,
                   DET, EMB, DET, DET+EMB,
                   wq13, bq1, nullptr, 0, q1_h, q1_l, MLP, 3*(DET+EMB)/BKP, MLP/BN, 1 };
        gemm_tc<<<dim3(MLP/BN, BATCH/BM, 1), 256, SMEM_TOT>>>(gq1, gq1);

        // po = q1 @ Wq2^T + bq2 -> qm | softplus+MIN_STD into out[...,256:512]
        GP gq2 = { q1_h, q1_l, q1_h, q1_l, MLP, MLP, BIG, MLP,
                   wq23, bq2, out + (size_t)t*BATCH*OUTW + 2*STO, OUTW,
                   nullptr, nullptr, 0, 3*MLP/BKP, 2*STO/BN, 2 };
        gemm_tc<<<dim3(2*STO/BN, BATCH/BM, 1), 256, SMEM_TOT>>>(gq2, gq2);

        if (t < T_STEPS - 1)
            stoc_pre<<<BATCH * DET / 256, 256>>>(out, noise, nont, actions, t);
    }

    // ---- prior head, batched over all T (off the recurrence) ----
    GP gp1 = { hT_h, hT_l, hT_h, hT_l, DET, DET, BIG, DET,
               wp13, bp1, nullptr, 0, p1_h, p1_l, MLP, 3*DET/BKP, MLP/BN, 1 };
    gemm_tc<<<dim3(MLP/BN, T_STEPS*BATCH/BM, 1), 256, SMEM_TOT>>>(gp1, gp1);

    GP gp2 = { p1_h, p1_l, p1_h, p1_l, MLP, MLP, BIG, MLP,
               wp23, bp2, out, OUTW, nullptr, nullptr, 0, 3*MLP/BKP, 2*STO/BN, 2 };
    gemm_tc<<<dim3(2*STO/BN, T_STEPS*BATCH/BM, 1), 256, SMEM_TOT>>>(gp2, gp2);
}

// round 7
// speedup vs baseline: 1.7321x; 1.7321x over previous
#include <cuda_runtime.h>
#include <cuda_bf16.h>
#include <math.h>
#include <stdint.h>

#define T_STEPS 64
#define BATCH   512
#define DET     1024
#define STO     128
#define EMB     1024
#define ACTD    16
#define MLP     1024
#define OUTW    1536            // 4*STO + DET
#define XIN     (STO + ACTD)    // 144
#define XINP    192             // padded K for input GEMM
#define MIN_STD 0.1f

// ---------------- GEMM tiling ----------------
#define BM 64
#define BN 64
#define BKP 64                  // K' elements per tile (bf16)
#define ATILE_B 8192            // 64 rows * 128B
#define STAGE_B 16384           // A tile + W tile
#define NSTAGE 4
#define SMEM_TOT (NSTAGE * STAGE_B)   // 65536

typedef __nv_bfloat16 bf16;

// ---------------- scratch (device globals; no allocation allowed) ----------------
__device__ float g_gi   [BATCH*3*DET];
__device__ float g_gh   [BATCH*3*DET];
__device__ float g_q2p  [8][BATCH*2*STO];

__device__ bf16 g_hprev_h[BATCH*DET],  g_hprev_l[BATCH*DET];
__device__ bf16 g_xin_h  [BATCH*XINP], g_xin_l  [BATCH*XINP];
__device__ bf16 g_x_h    [BATCH*DET],  g_x_l    [BATCH*DET];
__device__ bf16 g_q1_h   [BATCH*MLP],  g_q1_l   [BATCH*MLP];
__device__ bf16 g_hT_h   [(size_t)T_STEPS*BATCH*DET], g_hT_l[(size_t)T_STEPS*BATCH*DET];
__device__ bf16 g_obs_h  [(size_t)T_STEPS*BATCH*EMB], g_obs_l[(size_t)T_STEPS*BATCH*EMB];
__device__ bf16 g_p1_h   [(size_t)T_STEPS*BATCH*MLP], g_p1_l[(size_t)T_STEPS*BATCH*MLP];

// triple-K weights: [N, 3K] = [Wh | Wh | Wl]
__device__ bf16 g_Wih3[(size_t)3*DET*3*DET];
__device__ bf16 g_Whh3[(size_t)3*DET*3*DET];
__device__ bf16 g_Wq13[(size_t)MLP*3*(DET+EMB)];
__device__ bf16 g_Wq23[(size_t)2*STO*3*MLP];
__device__ bf16 g_Wp13[(size_t)MLP*3*DET];
__device__ bf16 g_Wp23[(size_t)2*STO*3*MLP];
__device__ bf16 g_Win3[(size_t)DET*3*XINP];

// ---------------- math helpers ----------------
__device__ __forceinline__ float elu_f(float v)      { return v > 0.0f ? v : expm1f(v); }
__device__ __forceinline__ float softplus_f(float v) { return fmaxf(v, 0.0f) + log1pf(expf(-fabsf(v))); }
__device__ __forceinline__ float sigmoid_f(float v)  { return __fdividef(1.0f, 1.0f + __expf(-v)); }
__device__ __forceinline__ float tanh_f(float x) {
    float e = __expf(-2.0f * fabsf(x));
    float r = __fdividef(1.0f - e, 1.0f + e);
    return x < 0.0f ? -r : r;
}

__device__ __forceinline__ uint32_t smem_u32(const void* p) {
    uint32_t a;
    asm("{ .reg .u64 t; cvta.to.shared.u64 t, %1; cvt.u32.u64 %0, t; }" : "=r"(a) : "l"(p));
    return a;
}
__device__ __forceinline__ void cp16(uint32_t dst, const void* src) {
    asm volatile("cp.async.cg.shared.global [%0], [%1], 16;" :: "r"(dst), "l"(src));
}
__device__ __forceinline__ void ldsm4(uint32_t* r, uint32_t addr) {
    asm volatile("ldmatrix.sync.aligned.m8n8.x4.shared.b16 {%0,%1,%2,%3}, [%4];"
                 : "=r"(r[0]), "=r"(r[1]), "=r"(r[2]), "=r"(r[3]) : "r"(addr));
}
__device__ __forceinline__ void mma16816(float* c, const uint32_t* a, uint32_t b0, uint32_t b1) {
    asm volatile("mma.sync.aligned.m16n8k16.row.col.f32.bf16.bf16.f32 "
                 "{%0,%1,%2,%3}, {%4,%5,%6,%7}, {%8,%9}, {%0,%1,%2,%3};"
                 : "+f"(c[0]), "+f"(c[1]), "+f"(c[2]), "+f"(c[3])
                 : "r"(a[0]), "r"(a[1]), "r"(a[2]), "r"(a[3]), "r"(b0), "r"(b1));
}
// Dekker split: hi = bf16 truncation, lo = bf16(v - hi) (residual exact in bf16)
__device__ __forceinline__ void split1(float v, uint16_t& h, uint16_t& l) {
    uint32_t u = __float_as_uint(v);
    float rem  = v - __uint_as_float(u & 0xFFFF0000u);
    h = (uint16_t)(u >> 16);
    l = (uint16_t)(__float_as_uint(rem) >> 16);
}
__device__ __forceinline__ void pack2(float a, float b, uint32_t& hi, uint32_t& lo) {
    uint32_t ua = __float_as_uint(a), ub = __float_as_uint(b);
    float ra = a - __uint_as_float(ua & 0xFFFF0000u);
    float rb = b - __uint_as_float(ub & 0xFFFF0000u);
    hi = (ua >> 16) | (ub & 0xFFFF0000u);
    lo = (__float_as_uint(ra) >> 16) | (__float_as_uint(rb) & 0xFFFF0000u);
}
__device__ __forceinline__ int swoff(int row, int u) {
    return row * 128 + (((u ^ (row & 7)) & 7) << 4);
}

// ---------------- GEMM params ----------------
struct GP {
    const bf16 *Ah0, *Al0, *Ah1, *Al1;   // A = K-concat(seg0, seg1); hi/lo sources
    int lda0, lda1, k0len, K;            // K = base (pre-triple) depth
    const bf16* W3;                      // [N, 3K]
    const float* bias;
    float* C; int ldc;                   // fp32 out (epi 0/2/3)
    bf16 *Ch, *Cl; int ldch;             // bf16 hi/lo out (epi 1)
    int nkb;                             // K'-tiles per split
    int nbx;                             // valid grid.x
    int epi;                             // 0 bias | 1 bias+elu->bf16 | 2 meanstd | 3 raw partial
    int nsplit;                          // split-K count (blockIdx.z = split)
    int psz;                             // partial stride (floats) for epi 3
};

// ---------------- bf16 HMMA GEMM: C = epi(A3 @ W3^T [+ bias]) ----------------
__global__ __launch_bounds__(128, 3)
void gemm_tc(GP p0, GP p1)
{
    GP p; int split = 0;
    if (p0.nsplit > 1) { p = p0; split = blockIdx.z; }
    else               { p = blockIdx.z ? p1 : p0; }
    if ((int)blockIdx.x >= p.nbx) return;

    extern __shared__ char smem[];
    const uint32_t sbase = smem_u32(smem);
    const int tid  = threadIdx.x, wid = tid >> 5, lane = tid & 31;
    const int m0   = blockIdx.y * BM, n0 = blockIdx.x * BN;
    const int wm   = (wid & 1) * 32, wn = (wid >> 1) * 32;
    const int lrow = tid >> 1;             // 0..63
    const int ub   = (tid & 1) * 4;        // unit base 0 or 4

    float acc[2][4][4];
    #pragma unroll
    for (int i = 0; i < 2; i++)
        #pragma unroll
        for (int j = 0; j < 4; j++)
            #pragma unroll
            for (int q = 0; q < 4; q++) acc[i][j][q] = 0.0f;

    auto load_stage = [&](int st, int kb) {
        const int kp = (split * p.nkb + kb) * BKP;
        const int phase = kp / p.K;
        const int khat  = kp - phase * p.K;
        const bf16* asrc; int acol, ald;
        if (khat < p.k0len) {
            asrc = (phase == 1) ? p.Al0 : p.Ah0; acol = khat; ald = p.lda0;
        } else {
            asrc = (phase == 1) ? p.Al1 : p.Ah1; acol = khat - p.k0len; ald = p.lda1;
        }
        const bf16* ap = asrc + (size_t)(m0 + lrow) * ald + acol + ub * 8;
        const bf16* wp = p.W3 + (size_t)(n0 + lrow) * (3 * p.K) + kp + ub * 8;
        const uint32_t As = sbase + st * STAGE_B;
        const uint32_t Ws = As + ATILE_B;
        #pragma unroll
        for (int i = 0; i < 4; i++) {
            const int off = swoff(lrow, ub + i);
            cp16(As + off, ap + i * 8);
            cp16(Ws + off, wp + i * 8);
        }
        asm volatile("cp.async.commit_group;" ::: "memory");
    };

    auto compute = [&](int st) {
        const uint32_t a_s = sbase + st * STAGE_B;
        const uint32_t w_s = a_s + ATILE_B;
        #pragma unroll
        for (int k16 = 0; k16 < 4; k16++) {
            uint32_t a[2][4], b[2][4];
            const int u = k16 * 2 + (lane >> 4);
            #pragma unroll
            for (int mi = 0; mi < 2; mi++)
                ldsm4(a[mi], a_s + swoff(wm + mi * 16 + (lane & 15), u));
            #pragma unroll
            for (int nj = 0; nj < 2; nj++)
                ldsm4(b[nj], w_s + swoff(wn + nj * 16 + (lane & 15), u));
            #pragma unroll
            for (int mi = 0; mi < 2; mi++)
                #pragma unroll
                for (int ni = 0; ni < 4; ni++) {
                    const int nj = ni >> 1, s = ni & 1;
                    mma16816(acc[mi][ni], a[mi], b[nj][s], b[nj][s + 2]);
                }
        }
    };

    int fetch = 0;
    #pragma unroll
    for (int s = 0; s < NSTAGE - 1; s++)
        if (fetch < p.nkb) { load_stage(s, fetch); fetch++; }

    for (int kb = 0; kb < p.nkb; kb++) {
        if (kb < p.nkb - 1) asm volatile("cp.async.wait_group %0;" :: "n"(NSTAGE - 2) : "memory");
        else                asm volatile("cp.async.wait_group 0;" ::: "memory");
        __syncthreads();
        if (fetch < p.nkb) { load_stage(fetch % NSTAGE, fetch); fetch++; }
        compute(kb % NSTAGE);
    }

    // ---- epilogue ----
    float* Cp = p.C;
    if (p.epi == 3) Cp += (size_t)split * p.psz;
    #pragma unroll
    for (int mi = 0; mi < 2; mi++) {
        const int r0 = m0 + wm + mi * 16 + (lane >> 2);
        const int r1 = r0 + 8;
        #pragma unroll
        for (int ni = 0; ni < 4; ni++) {
            const int col = n0 + wn + ni * 8 + (lane & 3) * 2;
            float e0 = acc[mi][ni][0], e1 = acc[mi][ni][1];
            float e2 = acc[mi][ni][2], e3 = acc[mi][ni][3];
            if (p.epi != 3) {
                float b0 = p.bias[col], b1 = p.bias[col + 1];
                e0 += b0; e1 += b1; e2 += b0; e3 += b1;
            }
            if (p.epi == 1) {
                e0 = elu_f(e0); e1 = elu_f(e1); e2 = elu_f(e2); e3 = elu_f(e3);
                uint32_t h01, l01, h23, l23;
                pack2(e0, e1, h01, l01);
                pack2(e2, e3, h23, l23);
                *(uint32_t*)(p.Ch + (size_t)r0 * p.ldch + col) = h01;
                *(uint32_t*)(p.Cl + (size_t)r0 * p.ldch + col) = l01;
                *(uint32_t*)(p.Ch + (size_t)r1 * p.ldch + col) = h23;
                *(uint32_t*)(p.Cl + (size_t)r1 * p.ldch + col) = l23;
            } else {
                if (p.epi == 2 && col >= 128) {
                    e0 = softplus_f(e0) + MIN_STD; e1 = softplus_f(e1) + MIN_STD;
                    e2 = softplus_f(e2) + MIN_STD; e3 = softplus_f(e3) + MIN_STD;
                }
                *(float2*)(Cp + (size_t)r0 * p.ldc + col) = make_float2(e0, e1);
                *(float2*)(Cp + (size_t)r1 * p.ldc + col) = make_float2(e2, e3);
            }
        }
    }
}

// ---------------- weight prep: W3 = [Wh | Wh | Wl] along K ----------------
__global__ void build_w3(const float* __restrict__ src, bf16* __restrict__ dst,
                         int K, int total)
{
    int i = blockIdx.x * blockDim.x + threadIdx.x;
    if (i >= total) return;
    int n = i / K, k = i - n * K;
    uint16_t h, l;
    split1(src[i], h, l);
    bf16* row = dst + (size_t)n * 3 * K;
    row[k]         = __ushort_as_bfloat16(h);
    row[K + k]     = __ushort_as_bfloat16(h);
    row[2 * K + k] = __ushort_as_bfloat16(l);
}
__global__ void build_w3_pad(const float* __restrict__ src, bf16* __restrict__ dst,
                             int Ksrc, int Kdst, int total)
{
    int i = blockIdx.x * blockDim.x + threadIdx.x;
    if (i >= total) return;
    int n = i / Kdst, k = i - n * Kdst;
    float v = (k < Ksrc) ? src[(size_t)n * Ksrc + k] : 0.0f;
    uint16_t h, l;
    split1(v, h, l);
    bf16* row = dst + (size_t)n * 3 * Kdst;
    row[k]            = __ushort_as_bfloat16(h);
    row[Kdst + k]     = __ushort_as_bfloat16(h);
    row[2 * Kdst + k] = __ushort_as_bfloat16(l);
}
__global__ void split_obs(const float* __restrict__ src, int total)
{
    int i = blockIdx.x * blockDim.x + threadIdx.x;
    if (i >= total) return;
    uint16_t h, l;
    split1(src[i], h, l);
    g_obs_h[i] = __ushort_as_bfloat16(h);
    g_obs_l[i] = __ushort_as_bfloat16(l);
}

// ---------------- elementwise kernels ----------------
__global__ void init_pre(const float* __restrict__ init_stoc,
                         const float* __restrict__ init_deter,
                         const float* __restrict__ nont,
                         const float* __restrict__ actions)
{
    int idx = blockIdx.x * blockDim.x + threadIdx.x;   // BATCH*DET
    int b = idx >> 10, j = idx & 1023;
    float nt = nont[b];
    uint16_t h, l;
    split1(init_deter[idx] * nt, h, l);
    g_hprev_h[idx] = __ushort_as_bfloat16(h);
    g_hprev_l[idx] = __ushort_as_bfloat16(l);
    if (j < XINP) {
        float v = 0.0f;
        if (j < STO)       v = init_stoc[b * STO + j] * nt;
        else if (j < XIN)  v = actions[(size_t)b * ACTD + (j - STO)];
        split1(v, h, l);
        g_xin_h[b * XINP + j] = __ushort_as_bfloat16(h);
        g_xin_l[b * XINP + j] = __ushort_as_bfloat16(l);
    }
}

// gates -> h; writes out[t], hT split, and hprev split for t+1
__global__ void gru_gates(const float* __restrict__ hsrc, int hstride,
                          const float* __restrict__ nont,
                          float* __restrict__ out, int t)
{
    int idx = blockIdx.x * blockDim.x + threadIdx.x;   // BATCH*DET
    int b = idx >> 10, j = idx & 1023;
    float nt = nont[t * BATCH + b];
    float hp = hsrc[(size_t)b * hstride + j] * nt;
    const float* gi = g_gi + (size_t)b * 3 * DET;
    const float* gh = g_gh + (size_t)b * 3 * DET;
    float r = sigmoid_f(gi[j]           + gh[j]);
    float z = sigmoid_f(gi[DET + j]     + gh[DET + j]);
    float n = tanh_f   (gi[2 * DET + j] + r * gh[2 * DET + j]);
    float h = (1.0f - z) * n + z * hp;
    out[((size_t)t * BATCH + b) * OUTW + 4 * STO + j] = h;
    uint16_t hh, hl;
    split1(h, hh, hl);
    size_t o = ((size_t)t * BATCH + b) * DET + j;
    g_hT_h[o] = __ushort_as_bfloat16(hh);
    g_hT_l[o] = __ushort_as_bfloat16(hl);
    if (t + 1 < T_STEPS) {
        split1(h * nont[(t + 1) * BATCH + b], hh, hl);
        g_hprev_h[idx] = __ushort_as_bfloat16(hh);
        g_hprev_l[idx] = __ushort_as_bfloat16(hl);
    }
}

// q2 split-K reduce + meanstd epi + stoc sample + xin prep for t+1
__global__ void q2red_stoc(const float* __restrict__ bq2,
                           const float* __restrict__ noise,
                           const float* __restrict__ nont,
                           const float* __restrict__ actions,
                           float* __restrict__ out, int t)
{
    int idx = blockIdx.x * blockDim.x + threadIdx.x;   // BATCH*128
    int b = idx >> 7, j = idx & 127;
    float sm = bq2[j], ss = bq2[128 + j];
    #pragma unroll
    for (int k = 0; k < 8; k++) {
        sm += g_q2p[k][b * 256 + j];
        ss += g_q2p[k][b * 256 + 128 + j];
    }
    float* row = out + ((size_t)t * BATCH + b) * OUTW;
    row[2 * STO + j] = sm;
    float qs = softplus_f(ss) + MIN_STD;
    row[3 * STO + j] = qs;
    if (t + 1 < T_STEPS) {
        float nt = nont[(t + 1) * BATCH + b];
        float st = (sm + qs * noise[((size_t)t * BATCH + b) * STO + j]) * nt;
        uint16_t h, l;
        split1(st, h, l);
        g_xin_h[b * XINP + j] = __ushort_as_bfloat16(h);
        g_xin_l[b * XINP + j] = __ushort_as_bfloat16(l);
        if (j < ACTD) {
            float a = actions[((size_t)(t + 1) * BATCH + b) * ACTD + j];
            split1(a, h, l);
            g_xin_h[b * XINP + STO + j] = __ushort_as_bfloat16(h);
            g_xin_l[b * XINP + STO + j] = __ushort_as_bfloat16(l);
        }
    }
}

// ---------------- launch ----------------
extern "C" void kernel_launch(void* const* d_in, const int* in_sizes, int n_in,
                              void* d_out, int out_size)
{
    const float* actions    = (const float*)d_in[0];
    const float* nont       = (const float*)d_in[1];
    const float* obs        = (const float*)d_in[2];
    const float* noise      = (const float*)d_in[3];
    const float* init_stoc  = (const float*)d_in[4];
    const float* init_deter = (const float*)d_in[5];
    const float* W_in = (const float*)d_in[6];
    const float* b_in = (const float*)d_in[7];
    const float* W_ih = (const float*)d_in[8];
    const float* W_hh = (const float*)d_in[9];
    const float* b_ih = (const float*)d_in[10];
    const float* b_hh = (const float*)d_in[11];
    const float* Wp1  = (const float*)d_in[12];
    const float* bp1  = (const float*)d_in[13];
    const float* Wp2  = (const float*)d_in[14];
    const float* bp2  = (const float*)d_in[15];
    const float* Wq1  = (const float*)d_in[16];
    const float* bq1  = (const float*)d_in[17];
    const float* Wq2  = (const float*)d_in[18];
    const float* bq2  = (const float*)d_in[19];
    float* out = (float*)d_out;

    float *p_gi, *p_gh, *p_q2p;
    cudaGetSymbolAddress((void**)&p_gi,  g_gi);
    cudaGetSymbolAddress((void**)&p_gh,  g_gh);
    cudaGetSymbolAddress((void**)&p_q2p, g_q2p);

    bf16 *hprev_h, *hprev_l, *xin_h, *xin_l, *x_h, *x_l, *q1_h, *q1_l;
    bf16 *hT_h, *hT_l, *obs_h, *obs_l, *p1_h, *p1_l;
    bf16 *wih3, *whh3, *wq13, *wq23, *wp13, *wp23, *win3;
    cudaGetSymbolAddress((void**)&hprev_h, g_hprev_h);
    cudaGetSymbolAddress((void**)&hprev_l, g_hprev_l);
    cudaGetSymbolAddress((void**)&xin_h,   g_xin_h);
    cudaGetSymbolAddress((void**)&xin_l,   g_xin_l);
    cudaGetSymbolAddress((void**)&x_h,     g_x_h);
    cudaGetSymbolAddress((void**)&x_l,     g_x_l);
    cudaGetSymbolAddress((void**)&q1_h,    g_q1_h);
    cudaGetSymbolAddress((void**)&q1_l,    g_q1_l);
    cudaGetSymbolAddress((void**)&hT_h,    g_hT_h);
    cudaGetSymbolAddress((void**)&hT_l,    g_hT_l);
    cudaGetSymbolAddress((void**)&obs_h,   g_obs_h);
    cudaGetSymbolAddress((void**)&obs_l,   g_obs_l);
    cudaGetSymbolAddress((void**)&p1_h,    g_p1_h);
    cudaGetSymbolAddress((void**)&p1_l,    g_p1_l);
    cudaGetSymbolAddress((void**)&wih3,    g_Wih3);
    cudaGetSymbolAddress((void**)&whh3,    g_Whh3);
    cudaGetSymbolAddress((void**)&wq13,    g_Wq13);
    cudaGetSymbolAddress((void**)&wq23,    g_Wq23);
    cudaGetSymbolAddress((void**)&wp13,    g_Wp13);
    cudaGetSymbolAddress((void**)&wp23,    g_Wp23);
    cudaGetSymbolAddress((void**)&win3,    g_Win3);

    cudaFuncSetAttribute(gemm_tc, cudaFuncAttributeMaxDynamicSharedMemorySize, SMEM_TOT);

    const int BIG = 1 << 28;
    // GP templates (t-dependent fields patched in loop)
    GP ggh = { hprev_h, hprev_l, hprev_h, hprev_l, DET, DET, BIG, DET,
               whh3, b_hh, p_gh, 3*DET, nullptr, nullptr, 0, 48, 48, 0, 1, 0 };
    GP ggx = { xin_h, xin_l, xin_h, xin_l, XINP, XINP, BIG, XINP,
               win3, b_in, nullptr, 0, x_h, x_l, DET, 9, 16, 1, 1, 0 };
    GP ggi = { x_h, x_l, x_h, x_l, DET, DET, BIG, DET,
               wih3, b_ih, p_gi, 3*DET, nullptr, nullptr, 0, 48, 48, 0, 1, 0 };
    GP gq2 = { q1_h, q1_l, q1_h, q1_l, MLP, MLP, BIG, MLP,
               wq23, nullptr, p_q2p, 2*STO, nullptr, nullptr, 0, 6, 4, 3, 8, BATCH*2*STO };

    // ---- prelude ordered so launches #5/#6 are the main GEMMs (ncu -s 5) ----
    build_w3<<<(3*DET*DET + 255)/256, 256>>>(W_ih, wih3, DET, 3*DET*DET);          // 1
    build_w3<<<(3*DET*DET + 255)/256, 256>>>(W_hh, whh3, DET, 3*DET*DET);          // 2
    build_w3_pad<<<(DET*XINP + 255)/256, 256>>>(W_in, win3, XIN, XINP, DET*XINP);  // 3
    init_pre<<<BATCH * DET / 256, 256>>>(init_stoc, init_deter, nont, actions);    // 4
    gemm_tc<<<dim3(48, 8, 2), 128, SMEM_TOT>>>(ggh, ggx);                          // 5  (t=0 gh+x)
    gemm_tc<<<dim3(48, 8, 1), 128, SMEM_TOT>>>(ggi, ggi);                          // 6  (t=0 gi)
    split_obs<<<(T_STEPS*BATCH*EMB + 255)/256, 256>>>(obs, T_STEPS*BATCH*EMB);     // 7
    build_w3<<<(MLP*(DET+EMB) + 255)/256, 256>>>(Wq1, wq13, DET+EMB, MLP*(DET+EMB));
    build_w3<<<(2*STO*MLP + 255)/256, 256>>>(Wq2, wq23, MLP, 2*STO*MLP);
    build_w3<<<(MLP*DET + 255)/256, 256>>>(Wp1, wp13, DET, MLP*DET);
    build_w3<<<(2*STO*MLP + 255)/256, 256>>>(Wp2, wp23, MLP, 2*STO*MLP);

    for (int t = 0; t < T_STEPS; t++) {
        if (t > 0) {
            gemm_tc<<<dim3(48, 8, 2), 128, SMEM_TOT>>>(ggh, ggx);   // gh + x
            gemm_tc<<<dim3(48, 8, 1), 128, SMEM_TOT>>>(ggi, ggi);   // gi
        }
        const float* hsrc = (t == 0) ? init_deter
                                     : out + (size_t)(t - 1) * BATCH * OUTW + 4 * STO;
        gru_gates<<<BATCH * DET / 256, 256>>>(hsrc, (t == 0) ? DET : OUTW, nont, out, t);

        GP gq1 = { hT_h + (size_t)t*BATCH*DET, hT_l + (size_t)t*BATCH*DET,
                   obs_h + (size_t)t*BATCH*EMB, obs_l + (size_t)t*BATCH*EMB,
                   DET, EMB, DET, DET+EMB,
                   wq13, bq1, nullptr, 0, q1_h, q1_l, MLP, 96, 16, 1, 1, 0 };
        gemm_tc<<<dim3(16, 8, 1), 128, SMEM_TOT>>>(gq1, gq1);

        gemm_tc<<<dim3(4, 8, 8), 128, SMEM_TOT>>>(gq2, gq2);        // q2 split-K8
        q2red_stoc<<<BATCH * 128 / 256, 256>>>(bq2, noise, nont, actions, out, t);
    }

    // ---- prior head, batched over all T (off the recurrence) ----
    GP gp1 = { hT_h, hT_l, hT_h, hT_l, DET, DET, BIG, DET,
               wp13, bp1, nullptr, 0, p1_h, p1_l, MLP, 48, 16, 1, 1, 0 };
    gemm_tc<<<dim3(16, 512, 1), 128, SMEM_TOT>>>(gp1, gp1);

    GP gp2 = { p1_h, p1_l, p1_h, p1_l, MLP, MLP, BIG, MLP,
               wp23, bp2, out, OUTW, nullptr, nullptr, 0, 48, 4, 2, 1, 0 };
    gemm_tc<<<dim3(4, 512, 1), 128, SMEM_TOT>>>(gp2, gp2);
}